// round 14
// baseline (speedup 1.0000x reference)
#include <cuda_runtime.h>
#include <cstdint>

#define Bq  256
#define Nn  2048
#define Dd  512
#define Hh  8
#define DHh 64
#define NK  2047            // N-1 keys per row
#define NCH 8               // n-chunks
#define CHR 256             // rows per chunk

// mask representation: 0 = int8, 1 = int32, 2 = float32
__device__ int g_mask_mode;

// scratch
__device__ float q_g[Hh * Bq * DHh];
__device__ float part_m[Bq * NCH * Hh];
__device__ float part_l[Bq * NCH * Hh];
__device__ float part_o[(size_t)Bq * NCH * Hh * DHh];

// ---- q projection (+ mask-mode detection in block 0): grid 512, 256 thr ----
__global__ __launch_bounds__(256) void q_proj_kernel(
    const float* __restrict__ ego, const float* __restrict__ W_q,
    const unsigned int* __restrict__ mw)
{
    __shared__ __align__(16) float ego_t[Dd][4];   // 8 KB, [d][j]
    __shared__ float redq[1024];                   // 4 KB
    __shared__ int a01, af;
    const int h     = blockIdx.x >> 6;   // 0..7
    const int bg    = blockIdx.x & 63;   // 0..63
    const int t     = threadIdx.x;
    const int k     = t & 63;
    const int dp    = t >> 6;            // 0..3, 128 d each
    const int bbase = bg * 4;

    if (blockIdx.x == 0) {
        if (t == 0) { a01 = 1; af = 1; }
        __syncthreads();
        int l01 = 1, lf = 1;
        #pragma unroll
        for (int i = 0; i < 4; ++i) {
            unsigned v = mw[t + i * 256];
            if (v != 0u && v != 1u) l01 = 0;
            if (v != 0u && v != 0x3F800000u) lf = 0;
        }
        if (!l01) atomicAnd(&a01, 0);
        if (!lf)  atomicAnd(&af, 0);
        __syncthreads();
        if (t == 0) g_mask_mode = a01 ? 1 : (af ? 2 : 0);
    }

    for (int i = t; i < 4 * Dd; i += 256) {
        const int j = i >> 9;        // 0..3
        const int d = i & 511;
        ego_t[d][j] = ego[(size_t)(bbase + j) * Dd + d];
    }
    __syncthreads();

    float4 acc = make_float4(0.f, 0.f, 0.f, 0.f);
    const float* wq = W_q + (size_t)h * Dd * DHh + k;
    #pragma unroll 8
    for (int d = dp * 128; d < dp * 128 + 128; ++d) {
        const float  wv = wq[(size_t)d * DHh];
        const float4 e  = *(const float4*)ego_t[d];   // broadcast, 1 LDS.128
        acc.x += e.x * wv;
        acc.y += e.y * wv;
        acc.z += e.z * wv;
        acc.w += e.w * wv;
    }
    redq[0 * 256 + t] = acc.x;
    redq[1 * 256 + t] = acc.y;
    redq[2 * 256 + t] = acc.z;
    redq[3 * 256 + t] = acc.w;
    __syncthreads();
    {
        const int j  = t >> 6;
        const int kk = t & 63;
        float s = redq[j * 256 + kk] + redq[j * 256 + 64 + kk]
                + redq[j * 256 + 128 + kk] + redq[j * 256 + 192 + kk];
        q_g[(size_t)h * (Bq * DHh) + (size_t)(bbase + j) * DHh + kk] = s;
    }
}

// ---- main: grid 2048 = (b, chunk), 256 threads; warp w = head w ----
// minBlocks=8 forces regs<=32 -> 8 CTAs/SM (was 6 at regs=40, occ 67%).
__global__ __launch_bounds__(256, 8) void mha_chunk_kernel(
    const void*  __restrict__ mask,
    const float* __restrict__ keys,     // (H,B,NK,DH)
    const float* __restrict__ value)    // (B,NK,DH)
{
    __shared__ __align__(16) float q_sm[Hh * DHh];   // 2 KB
    __shared__ float sc[Hh * CHR];                   // 8 KB
    __shared__ float red[4 * 512];                   // 8 KB
    __shared__ unsigned char msk_sm[CHR];

    const int bid  = blockIdx.x;
    const int b    = bid >> 3;
    const int c    = bid & 7;
    const int n0   = c * CHR;
    const int rows = (NK - n0 < CHR) ? (NK - n0) : CHR;
    const int t    = threadIdx.x;
    const int w    = t >> 5;        // head
    const int lane = t & 31;

    // stage q for all heads
    for (int i = t; i < Hh * DHh; i += 256)
        q_sm[i] = q_g[(size_t)(i >> 6) * (Bq * DHh) + (size_t)b * DHh + (i & 63)];

    // stage mask chunk
    {
        const int mode = g_mask_mode;
        if (mode == 0) {
            const unsigned char* m8 = (const unsigned char*)mask + (size_t)b * Nn + 1 + n0;
            for (int r = t; r < rows; r += 256) msk_sm[r] = m8[r];
        } else if (mode == 1) {
            const int* m32 = (const int*)mask + (size_t)b * Nn + 1 + n0;
            for (int r = t; r < rows; r += 256) msk_sm[r] = (unsigned char)(m32[r] != 0);
        } else {
            const float* mf = (const float*)mask + (size_t)b * Nn + 1 + n0;
            for (int r = t; r < rows; r += 256) msk_sm[r] = (unsigned char)(mf[r] != 0.0f);
        }
    }
    __syncthreads();

    // ---- Phase 1: warp w computes scores for head w over this chunk ----
    const int l8 = lane & 7;        // column-eighth
    const int rq = lane >> 3;       // row within quad
    const float* kb = keys + ((size_t)(w * Bq + b) * NK + n0) * DHh;
    const float4 qA = *(const float4*)(q_sm + w * DHh + l8 * 4);
    const float4 qB = *(const float4*)(q_sm + w * DHh + l8 * 4 + 32);

    float wm = -3.0e38f;

    #pragma unroll 2
    for (int it = 0; it < CHR / 4; ++it) {
        const int  r = it * 4 + rq;
        const bool v = r < rows;
        const float* kp = kb + (size_t)r * DHh + l8 * 4;
        float4 a  = make_float4(0.f, 0.f, 0.f, 0.f);
        float4 bb = make_float4(0.f, 0.f, 0.f, 0.f);
        if (v) {
            a  = __ldcs((const float4*)kp);        // bytes 0..127 of row (coalesced)
            bb = __ldcs((const float4*)(kp + 32)); // bytes 128..255
        }
        float s = a.x*qA.x + a.y*qA.y + a.z*qA.z + a.w*qA.w
                + bb.x*qB.x + bb.y*qB.y + bb.z*qB.z + bb.w*qB.w;
        s += __shfl_xor_sync(0xffffffffu, s, 1);
        s += __shfl_xor_sync(0xffffffffu, s, 2);
        s += __shfl_xor_sync(0xffffffffu, s, 4);
        if (v) {
            s *= 0.125f;
            if (!msk_sm[r]) s = -1.0e30f;
            wm = fmaxf(wm, s);
            if (l8 == 0) sc[w * CHR + r] = s;
        }
    }
    // warp max (groups of 8 already share values)
    wm = fmaxf(wm, __shfl_xor_sync(0xffffffffu, wm, 8));
    wm = fmaxf(wm, __shfl_xor_sync(0xffffffffu, wm, 16));
    const float m = wm;

    // ---- Phase 2: exp + sum (per warp/head) ----
    float ls = 0.f;
    for (int r = lane; r < rows; r += 32) {
        float p = __expf(sc[w * CHR + r] - m);
        sc[w * CHR + r] = p;
        ls += p;
    }
    #pragma unroll
    for (int o = 16; o; o >>= 1)
        ls += __shfl_xor_sync(0xffffffffu, ls, o);
    if (lane == 0) {
        part_m[bid * Hh + w] = m;
        part_l[bid * Hh + w] = ls;
    }
    __syncthreads();   // all heads' p ready

    // ---- Phase 3: o_partial[h][k] = sum_r p[h][r] * v[r][k] ----
    {
        const int k  = t & 63;
        const int q3 = t >> 6;
        const float* vp = value + ((size_t)b * NK + n0) * DHh + k;
        float acc[8] = {0, 0, 0, 0, 0, 0, 0, 0};
        if (rows == CHR) {
            #pragma unroll 4
            for (int r = q3; r < CHR; r += 4) {
                const float vv = __ldcs(vp + (size_t)r * DHh);
                #pragma unroll
                for (int h = 0; h < 8; ++h) acc[h] += sc[h * CHR + r] * vv;
            }
        } else {
            for (int r = q3; r < rows; r += 4) {
                const float vv = __ldcs(vp + (size_t)r * DHh);
                #pragma unroll
                for (int h = 0; h < 8; ++h) acc[h] += sc[h * CHR + r] * vv;
            }
        }
        #pragma unroll
        for (int h = 0; h < 8; ++h) red[q3 * 512 + h * 64 + k] = acc[h];
    }
    __syncthreads();
    for (int j = t; j < 512; j += 256) {
        float s = red[j] + red[512 + j] + red[1024 + j] + red[1536 + j];
        part_o[(size_t)bid * 512 + j] = s;   // j = h*64+k
    }
}

// ---- combine: grid 256 (b), 256 threads; warp w = head w ----
__global__ __launch_bounds__(256) void combine_kernel(float* __restrict__ out)
{
    const int b    = blockIdx.x;
    const int t    = threadIdx.x;
    const int w    = t >> 5;
    const int lane = t & 31;

    float mv[NCH], lv[NCH];
    #pragma unroll
    for (int c = 0; c < NCH; ++c) {
        mv[c] = part_m[(b * NCH + c) * Hh + w];
        lv[c] = part_l[(b * NCH + c) * Hh + w];
    }
    float M = mv[0];
    #pragma unroll
    for (int c = 1; c < NCH; ++c) M = fmaxf(M, mv[c]);
    float L = 0.f;
    float ws[NCH];
    #pragma unroll
    for (int c = 0; c < NCH; ++c) {
        ws[c] = __expf(mv[c] - M);
        L += lv[c] * ws[c];
    }
    const float invL = 1.0f / L;

    #pragma unroll
    for (int kk = 0; kk < 2; ++kk) {
        const int k = lane + kk * 32;
        float a = 0.f;
        #pragma unroll
        for (int c = 0; c < NCH; ++c)
            a += ws[c] * part_o[(size_t)(b * NCH + c) * 512 + w * 64 + k];
        out[(size_t)b * Dd + w * DHh + k] = a * invL;
    }
}

extern "C" void kernel_launch(void* const* d_in, const int* in_sizes, int n_in,
                              void* d_out, int out_size) {
    // Bind inputs by element count (all five pairwise distinct).
    const float* ego   = nullptr;
    const void*  mask  = nullptr;
    const float* keys  = nullptr;
    const float* value = nullptr;
    const float* W_q   = nullptr;

    for (int i = 0; i < n_in; ++i) {
        switch (in_sizes[i]) {
            case Bq * Dd:                 ego   = (const float*)d_in[i]; break; // 131072
            case Bq * Nn:                 mask  = d_in[i];               break; // 524288
            case Hh * Bq * NK * DHh:      keys  = (const float*)d_in[i]; break; // 268173312
            case Bq * NK * DHh:           value = (const float*)d_in[i]; break; // 33521664
            case Hh * Dd * DHh:           W_q   = (const float*)d_in[i]; break; // 262144
            default: break;
        }
    }

    float* out = (float*)d_out;

    q_proj_kernel<<<512, 256>>>(ego, W_q, (const unsigned int*)mask);
    mha_chunk_kernel<<<Bq * NCH, 256>>>(mask, keys, value);
    combine_kernel<<<Bq, 256>>>(out);
}

// round 15
// speedup vs baseline: 1.0098x; 1.0098x over previous
#include <cuda_runtime.h>
#include <cstdint>

#define Bq  256
#define Nn  2048
#define Dd  512
#define Hh  8
#define DHh 64
#define NK  2047            // N-1 keys per row
#define NCH 8               // n-chunks
#define CHR 256             // rows per chunk

// mask representation: 0 = int8, 1 = int32, 2 = float32
__device__ int g_mask_mode;

// scratch
__device__ float q_g[Hh * Bq * DHh];
__device__ float part_m[Bq * NCH * Hh];
__device__ float part_l[Bq * NCH * Hh];
__device__ float part_o[(size_t)Bq * NCH * Hh * DHh];

// ---- q projection (+ mask-mode detection in block 0): grid 512, 256 thr ----
__global__ __launch_bounds__(256) void q_proj_kernel(
    const float* __restrict__ ego, const float* __restrict__ W_q,
    const unsigned int* __restrict__ mw)
{
    __shared__ __align__(16) float ego_t[Dd][4];   // 8 KB, [d][j]
    __shared__ float redq[1024];                   // 4 KB
    __shared__ int a01, af;
    const int h     = blockIdx.x >> 6;   // 0..7
    const int bg    = blockIdx.x & 63;   // 0..63
    const int t     = threadIdx.x;
    const int k     = t & 63;
    const int dp    = t >> 6;            // 0..3, 128 d each
    const int bbase = bg * 4;

    if (blockIdx.x == 0) {
        if (t == 0) { a01 = 1; af = 1; }
        __syncthreads();
        int l01 = 1, lf = 1;
        #pragma unroll
        for (int i = 0; i < 4; ++i) {
            unsigned v = mw[t + i * 256];
            if (v != 0u && v != 1u) l01 = 0;
            if (v != 0u && v != 0x3F800000u) lf = 0;
        }
        if (!l01) atomicAnd(&a01, 0);
        if (!lf)  atomicAnd(&af, 0);
        __syncthreads();
        if (t == 0) g_mask_mode = a01 ? 1 : (af ? 2 : 0);
    }

    for (int i = t; i < 4 * Dd; i += 256) {
        const int j = i >> 9;        // 0..3
        const int d = i & 511;
        ego_t[d][j] = ego[(size_t)(bbase + j) * Dd + d];
    }
    __syncthreads();

    float4 acc = make_float4(0.f, 0.f, 0.f, 0.f);
    const float* wq = W_q + (size_t)h * Dd * DHh + k;
    #pragma unroll 8
    for (int d = dp * 128; d < dp * 128 + 128; ++d) {
        const float  wv = wq[(size_t)d * DHh];
        const float4 e  = *(const float4*)ego_t[d];   // broadcast, 1 LDS.128
        acc.x += e.x * wv;
        acc.y += e.y * wv;
        acc.z += e.z * wv;
        acc.w += e.w * wv;
    }
    redq[0 * 256 + t] = acc.x;
    redq[1 * 256 + t] = acc.y;
    redq[2 * 256 + t] = acc.z;
    redq[3 * 256 + t] = acc.w;
    __syncthreads();
    {
        const int j  = t >> 6;
        const int kk = t & 63;
        float s = redq[j * 256 + kk] + redq[j * 256 + 64 + kk]
                + redq[j * 256 + 128 + kk] + redq[j * 256 + 192 + kk];
        q_g[(size_t)h * (Bq * DHh) + (size_t)(bbase + j) * DHh + kk] = s;
    }
}

// ---- main: grid 2048 = (b, chunk), 256 threads; warp w = head w ----
__global__ __launch_bounds__(256) void mha_chunk_kernel(
    const void*  __restrict__ mask,
    const float* __restrict__ keys,     // (H,B,NK,DH)
    const float* __restrict__ value)    // (B,NK,DH)
{
    __shared__ __align__(16) float q_sm[Hh * DHh];   // 2 KB
    __shared__ float sc[Hh * CHR];                   // 8 KB
    __shared__ float red[4 * 512];                   // 8 KB
    __shared__ unsigned char msk_sm[CHR];

    const int bid  = blockIdx.x;
    const int b    = bid >> 3;
    const int c    = bid & 7;
    const int n0   = c * CHR;
    const int rows = (NK - n0 < CHR) ? (NK - n0) : CHR;
    const int t    = threadIdx.x;
    const int w    = t >> 5;        // head
    const int lane = t & 31;

    // stage q for all heads
    for (int i = t; i < Hh * DHh; i += 256)
        q_sm[i] = q_g[(size_t)(i >> 6) * (Bq * DHh) + (size_t)b * DHh + (i & 63)];

    // stage mask chunk
    {
        const int mode = g_mask_mode;
        if (mode == 0) {
            const unsigned char* m8 = (const unsigned char*)mask + (size_t)b * Nn + 1 + n0;
            for (int r = t; r < rows; r += 256) msk_sm[r] = m8[r];
        } else if (mode == 1) {
            const int* m32 = (const int*)mask + (size_t)b * Nn + 1 + n0;
            for (int r = t; r < rows; r += 256) msk_sm[r] = (unsigned char)(m32[r] != 0);
        } else {
            const float* mf = (const float*)mask + (size_t)b * Nn + 1 + n0;
            for (int r = t; r < rows; r += 256) msk_sm[r] = (unsigned char)(mf[r] != 0.0f);
        }
    }
    __syncthreads();

    // ---- Phase 1: warp w computes scores for head w over this chunk ----
    const int l8 = lane & 7;        // column-eighth
    const int rq = lane >> 3;       // row within quad
    const float* kb = keys + ((size_t)(w * Bq + b) * NK + n0) * DHh;
    const float4 qA = *(const float4*)(q_sm + w * DHh + l8 * 4);
    const float4 qB = *(const float4*)(q_sm + w * DHh + l8 * 4 + 32);

    float wm = -3.0e38f;

    #pragma unroll 2
    for (int it = 0; it < CHR / 4; ++it) {
        const int  r = it * 4 + rq;
        const bool v = r < rows;
        const float* kp = kb + (size_t)r * DHh + l8 * 4;
        float4 a  = make_float4(0.f, 0.f, 0.f, 0.f);
        float4 bb = make_float4(0.f, 0.f, 0.f, 0.f);
        if (v) {
            a  = __ldcs((const float4*)kp);        // bytes 0..127 of row (coalesced)
            bb = __ldcs((const float4*)(kp + 32)); // bytes 128..255
        }
        float s = a.x*qA.x + a.y*qA.y + a.z*qA.z + a.w*qA.w
                + bb.x*qB.x + bb.y*qB.y + bb.z*qB.z + bb.w*qB.w;
        s += __shfl_xor_sync(0xffffffffu, s, 1);
        s += __shfl_xor_sync(0xffffffffu, s, 2);
        s += __shfl_xor_sync(0xffffffffu, s, 4);
        if (v) {
            s *= 0.125f;
            if (!msk_sm[r]) s = -1.0e30f;
            wm = fmaxf(wm, s);
            if (l8 == 0) sc[w * CHR + r] = s;
        }
    }
    // warp max (groups of 8 already share values)
    wm = fmaxf(wm, __shfl_xor_sync(0xffffffffu, wm, 8));
    wm = fmaxf(wm, __shfl_xor_sync(0xffffffffu, wm, 16));
    const float m = wm;

    // ---- Phase 2: exp + sum (per warp/head) ----
    float ls = 0.f;
    for (int r = lane; r < rows; r += 32) {
        float p = __expf(sc[w * CHR + r] - m);
        sc[w * CHR + r] = p;
        ls += p;
    }
    #pragma unroll
    for (int o = 16; o; o >>= 1)
        ls += __shfl_xor_sync(0xffffffffu, ls, o);
    if (lane == 0) {
        part_m[bid * Hh + w] = m;
        part_l[bid * Hh + w] = ls;
    }
    __syncthreads();   // all heads' p ready

    // ---- Phase 3: o_partial[h][k] = sum_r p[h][r] * v[r][k] ----
    // Two passes of 4 heads each: halves live registers (acc[4] + 4 vv)
    // so occupancy rises organically (no spills). Pass 2 re-reads the
    // 64KB value chunk from L2 (hot after pass 1).
    {
        const int k  = t & 63;
        const int q3 = t >> 6;
        const float* vp = value + ((size_t)b * NK + n0) * DHh + k;

        #pragma unroll
        for (int hg = 0; hg < 2; ++hg) {
            const int h0 = hg * 4;
            float acc[4] = {0, 0, 0, 0};
            if (rows == CHR) {
                #pragma unroll 4
                for (int r = q3; r < CHR; r += 4) {
                    const float vv = vp[(size_t)r * DHh];
                    #pragma unroll
                    for (int h = 0; h < 4; ++h)
                        acc[h] += sc[(h0 + h) * CHR + r] * vv;
                }
            } else {
                for (int r = q3; r < rows; r += 4) {
                    const float vv = vp[(size_t)r * DHh];
                    #pragma unroll
                    for (int h = 0; h < 4; ++h)
                        acc[h] += sc[(h0 + h) * CHR + r] * vv;
                }
            }
            #pragma unroll
            for (int h = 0; h < 4; ++h)
                red[q3 * 512 + (h0 + h) * 64 + k] = acc[h];
        }
    }
    __syncthreads();
    for (int j = t; j < 512; j += 256) {
        float s = red[j] + red[512 + j] + red[1024 + j] + red[1536 + j];
        part_o[(size_t)bid * 512 + j] = s;   // j = h*64+k
    }
}

// ---- combine: grid 256 (b), 256 threads; warp w = head w ----
__global__ __launch_bounds__(256) void combine_kernel(float* __restrict__ out)
{
    const int b    = blockIdx.x;
    const int t    = threadIdx.x;
    const int w    = t >> 5;
    const int lane = t & 31;

    float mv[NCH], lv[NCH];
    #pragma unroll
    for (int c = 0; c < NCH; ++c) {
        mv[c] = part_m[(b * NCH + c) * Hh + w];
        lv[c] = part_l[(b * NCH + c) * Hh + w];
    }
    float M = mv[0];
    #pragma unroll
    for (int c = 1; c < NCH; ++c) M = fmaxf(M, mv[c]);
    float L = 0.f;
    float ws[NCH];
    #pragma unroll
    for (int c = 0; c < NCH; ++c) {
        ws[c] = __expf(mv[c] - M);
        L += lv[c] * ws[c];
    }
    const float invL = 1.0f / L;

    #pragma unroll
    for (int kk = 0; kk < 2; ++kk) {
        const int k = lane + kk * 32;
        float a = 0.f;
        #pragma unroll
        for (int c = 0; c < NCH; ++c)
            a += ws[c] * part_o[(size_t)(b * NCH + c) * 512 + w * 64 + k];
        out[(size_t)b * Dd + w * DHh + k] = a * invL;
    }
}

extern "C" void kernel_launch(void* const* d_in, const int* in_sizes, int n_in,
                              void* d_out, int out_size) {
    // Bind inputs by element count (all five pairwise distinct).
    const float* ego   = nullptr;
    const void*  mask  = nullptr;
    const float* keys  = nullptr;
    const float* value = nullptr;
    const float* W_q   = nullptr;

    for (int i = 0; i < n_in; ++i) {
        switch (in_sizes[i]) {
            case Bq * Dd:                 ego   = (const float*)d_in[i]; break; // 131072
            case Bq * Nn:                 mask  = d_in[i];               break; // 524288
            case Hh * Bq * NK * DHh:      keys  = (const float*)d_in[i]; break; // 268173312
            case Bq * NK * DHh:           value = (const float*)d_in[i]; break; // 33521664
            case Hh * Dd * DHh:           W_q   = (const float*)d_in[i]; break; // 262144
            default: break;
        }
    }

    float* out = (float*)d_out;

    q_proj_kernel<<<512, 256>>>(ego, W_q, (const unsigned int*)mask);
    mha_chunk_kernel<<<Bq * NCH, 256>>>(mask, keys, value);
    combine_kernel<<<Bq, 256>>>(out);
}

// round 16
// speedup vs baseline: 1.0985x; 1.0879x over previous
#include <cuda_runtime.h>
#include <cstdint>

#define Bq  256
#define Nn  2048
#define Dd  512
#define Hh  8
#define DHh 64
#define NK  2047            // N-1 keys per row
#define NCH 8               // n-chunks
#define CHR 256             // rows per chunk

// mask representation: 0 = int8, 1 = int32, 2 = float32
__device__ int g_mask_mode;

// scratch
__device__ float q_g[Hh * Bq * DHh];
__device__ float part_m[Bq * NCH * Hh];
__device__ float part_l[Bq * NCH * Hh];
__device__ float part_o[(size_t)Bq * NCH * Hh * DHh];

// ---- q projection (+ mask detect in block 0): grid 1024 = (h, b-pair) ----
// 2 b's per CTA; inner loop: 1 LDG + 1 LDS.64 broadcast + 2 FMA per d.
__global__ __launch_bounds__(256) void q_proj_kernel(
    const float* __restrict__ ego, const float* __restrict__ W_q,
    const unsigned int* __restrict__ mw)
{
    __shared__ __align__(16) float ego_t[Dd][2];   // 4 KB, [d][j]
    __shared__ float redq[512];                    // 2 KB
    __shared__ int a01, af;
    const int h     = blockIdx.x >> 7;   // 0..7
    const int bg    = blockIdx.x & 127;  // 0..127
    const int t     = threadIdx.x;
    const int k     = t & 63;
    const int dp    = t >> 6;            // 0..3, 128 d each
    const int bbase = bg * 2;

    if (blockIdx.x == 0) {
        if (t == 0) { a01 = 1; af = 1; }
        __syncthreads();
        int l01 = 1, lf = 1;
        #pragma unroll
        for (int i = 0; i < 4; ++i) {
            unsigned v = mw[t + i * 256];
            if (v != 0u && v != 1u) l01 = 0;
            if (v != 0u && v != 0x3F800000u) lf = 0;
        }
        if (!l01) atomicAnd(&a01, 0);
        if (!lf)  atomicAnd(&af, 0);
        __syncthreads();
        if (t == 0) g_mask_mode = a01 ? 1 : (af ? 2 : 0);
    }

    // stage ego transposed: ego_t[d][j] = ego[bbase+j][d]
    for (int i = t; i < 2 * Dd; i += 256) {
        const int j = i >> 9;        // 0..1
        const int d = i & 511;
        ego_t[d][j] = ego[(size_t)(bbase + j) * Dd + d];
    }
    __syncthreads();

    float2 acc = make_float2(0.f, 0.f);
    const float* wq = W_q + (size_t)h * Dd * DHh + k;
    #pragma unroll 8
    for (int d = dp * 128; d < dp * 128 + 128; ++d) {
        const float  wv = wq[(size_t)d * DHh];
        const float2 e  = *(const float2*)ego_t[d];   // LDS.64 broadcast
        acc.x += e.x * wv;
        acc.y += e.y * wv;
    }
    redq[0 * 256 + t] = acc.x;
    redq[1 * 256 + t] = acc.y;
    __syncthreads();
    if (t < 128) {
        const int j  = t >> 6;       // 0..1
        const int kk = t & 63;
        float s = redq[j * 256 + kk] + redq[j * 256 + 64 + kk]
                + redq[j * 256 + 128 + kk] + redq[j * 256 + 192 + kk];
        q_g[(size_t)h * (Bq * DHh) + (size_t)(bbase + j) * DHh + kk] = s;
    }
}

// ---- main: grid 2048 = (b, chunk), 256 threads; warp w = head w ----
// (R12 configuration verbatim — best measured.)
__global__ __launch_bounds__(256) void mha_chunk_kernel(
    const void*  __restrict__ mask,
    const float* __restrict__ keys,     // (H,B,NK,DH)
    const float* __restrict__ value)    // (B,NK,DH)
{
    __shared__ __align__(16) float q_sm[Hh * DHh];   // 2 KB
    __shared__ float sc[Hh * CHR];                   // 8 KB
    __shared__ float red[4 * 512];                   // 8 KB
    __shared__ unsigned char msk_sm[CHR];

    const int bid  = blockIdx.x;
    const int b    = bid >> 3;
    const int c    = bid & 7;
    const int n0   = c * CHR;
    const int rows = (NK - n0 < CHR) ? (NK - n0) : CHR;
    const int t    = threadIdx.x;
    const int w    = t >> 5;        // head
    const int lane = t & 31;

    // stage q for all heads
    for (int i = t; i < Hh * DHh; i += 256)
        q_sm[i] = q_g[(size_t)(i >> 6) * (Bq * DHh) + (size_t)b * DHh + (i & 63)];

    // stage mask chunk
    {
        const int mode = g_mask_mode;
        if (mode == 0) {
            const unsigned char* m8 = (const unsigned char*)mask + (size_t)b * Nn + 1 + n0;
            for (int r = t; r < rows; r += 256) msk_sm[r] = m8[r];
        } else if (mode == 1) {
            const int* m32 = (const int*)mask + (size_t)b * Nn + 1 + n0;
            for (int r = t; r < rows; r += 256) msk_sm[r] = (unsigned char)(m32[r] != 0);
        } else {
            const float* mf = (const float*)mask + (size_t)b * Nn + 1 + n0;
            for (int r = t; r < rows; r += 256) msk_sm[r] = (unsigned char)(mf[r] != 0.0f);
        }
    }
    __syncthreads();

    // ---- Phase 1: warp w computes scores for head w over this chunk ----
    const int l8 = lane & 7;        // column-eighth
    const int rq = lane >> 3;       // row within quad
    const float* kb = keys + ((size_t)(w * Bq + b) * NK + n0) * DHh;
    const float4 qA = *(const float4*)(q_sm + w * DHh + l8 * 4);
    const float4 qB = *(const float4*)(q_sm + w * DHh + l8 * 4 + 32);

    float wm = -3.0e38f;

    #pragma unroll 2
    for (int it = 0; it < CHR / 4; ++it) {
        const int  r = it * 4 + rq;
        const bool v = r < rows;
        const float* kp = kb + (size_t)r * DHh + l8 * 4;
        float4 a  = make_float4(0.f, 0.f, 0.f, 0.f);
        float4 bb = make_float4(0.f, 0.f, 0.f, 0.f);
        if (v) {
            a  = __ldcs((const float4*)kp);        // bytes 0..127 of row (coalesced)
            bb = __ldcs((const float4*)(kp + 32)); // bytes 128..255
        }
        float s = a.x*qA.x + a.y*qA.y + a.z*qA.z + a.w*qA.w
                + bb.x*qB.x + bb.y*qB.y + bb.z*qB.z + bb.w*qB.w;
        s += __shfl_xor_sync(0xffffffffu, s, 1);
        s += __shfl_xor_sync(0xffffffffu, s, 2);
        s += __shfl_xor_sync(0xffffffffu, s, 4);
        if (v) {
            s *= 0.125f;
            if (!msk_sm[r]) s = -1.0e30f;
            wm = fmaxf(wm, s);
            if (l8 == 0) sc[w * CHR + r] = s;
        }
    }
    // warp max (groups of 8 already share values)
    wm = fmaxf(wm, __shfl_xor_sync(0xffffffffu, wm, 8));
    wm = fmaxf(wm, __shfl_xor_sync(0xffffffffu, wm, 16));
    const float m = wm;

    // ---- Phase 2: exp + sum (per warp/head) ----
    float ls = 0.f;
    for (int r = lane; r < rows; r += 32) {
        float p = __expf(sc[w * CHR + r] - m);
        sc[w * CHR + r] = p;
        ls += p;
    }
    #pragma unroll
    for (int o = 16; o; o >>= 1)
        ls += __shfl_xor_sync(0xffffffffu, ls, o);
    if (lane == 0) {
        part_m[bid * Hh + w] = m;
        part_l[bid * Hh + w] = ls;
    }
    __syncthreads();   // all heads' p ready

    // ---- Phase 3: o_partial[h][k] = sum_r p[h][r] * v[r][k] ----
    {
        const int k  = t & 63;
        const int q3 = t >> 6;
        const float* vp = value + ((size_t)b * NK + n0) * DHh + k;
        float acc[8] = {0, 0, 0, 0, 0, 0, 0, 0};
        if (rows == CHR) {
            #pragma unroll 4
            for (int r = q3; r < CHR; r += 4) {
                const float vv = __ldcs(vp + (size_t)r * DHh);
                #pragma unroll
                for (int h = 0; h < 8; ++h) acc[h] += sc[h * CHR + r] * vv;
            }
        } else {
            for (int r = q3; r < rows; r += 4) {
                const float vv = __ldcs(vp + (size_t)r * DHh);
                #pragma unroll
                for (int h = 0; h < 8; ++h) acc[h] += sc[h * CHR + r] * vv;
            }
        }
        #pragma unroll
        for (int h = 0; h < 8; ++h) red[q3 * 512 + h * 64 + k] = acc[h];
    }
    __syncthreads();
    for (int j = t; j < 512; j += 256) {
        float s = red[j] + red[512 + j] + red[1024 + j] + red[1536 + j];
        part_o[(size_t)bid * 512 + j] = s;   // j = h*64+k
    }
}

// ---- combine: grid 256 (b), 256 threads; warp w = head w ----
__global__ __launch_bounds__(256) void combine_kernel(float* __restrict__ out)
{
    const int b    = blockIdx.x;
    const int t    = threadIdx.x;
    const int w    = t >> 5;
    const int lane = t & 31;

    float mv[NCH], lv[NCH];
    #pragma unroll
    for (int c = 0; c < NCH; ++c) {
        mv[c] = part_m[(b * NCH + c) * Hh + w];
        lv[c] = part_l[(b * NCH + c) * Hh + w];
    }
    float M = mv[0];
    #pragma unroll
    for (int c = 1; c < NCH; ++c) M = fmaxf(M, mv[c]);
    float L = 0.f;
    float ws[NCH];
    #pragma unroll
    for (int c = 0; c < NCH; ++c) {
        ws[c] = __expf(mv[c] - M);
        L += lv[c] * ws[c];
    }
    const float invL = 1.0f / L;

    #pragma unroll
    for (int kk = 0; kk < 2; ++kk) {
        const int k = lane + kk * 32;
        float a = 0.f;
        #pragma unroll
        for (int c = 0; c < NCH; ++c)
            a += ws[c] * part_o[(size_t)(b * NCH + c) * 512 + w * 64 + k];
        out[(size_t)b * Dd + w * DHh + k] = a * invL;
    }
}

extern "C" void kernel_launch(void* const* d_in, const int* in_sizes, int n_in,
                              void* d_out, int out_size) {
    // Bind inputs by element count (all five pairwise distinct).
    const float* ego   = nullptr;
    const void*  mask  = nullptr;
    const float* keys  = nullptr;
    const float* value = nullptr;
    const float* W_q   = nullptr;

    for (int i = 0; i < n_in; ++i) {
        switch (in_sizes[i]) {
            case Bq * Dd:                 ego   = (const float*)d_in[i]; break; // 131072
            case Bq * Nn:                 mask  = d_in[i];               break; // 524288
            case Hh * Bq * NK * DHh:      keys  = (const float*)d_in[i]; break; // 268173312
            case Bq * NK * DHh:           value = (const float*)d_in[i]; break; // 33521664
            case Hh * Dd * DHh:           W_q   = (const float*)d_in[i]; break; // 262144
            default: break;
        }
    }

    float* out = (float*)d_out;

    q_proj_kernel<<<1024, 256>>>(ego, W_q, (const unsigned int*)mask);
    mha_chunk_kernel<<<Bq * NCH, 256>>>(mask, keys, value);
    combine_kernel<<<Bq, 256>>>(out);
}